// round 9
// baseline (speedup 1.0000x reference)
#include <cuda_runtime.h>

#define BB    2048
#define TR    2080   // row length of transposed qx (floats); rows zero-padded
#define TROUT 2048   // row length of transposed output

__device__ float g_qxT[(size_t)BB * TR];
__device__ float g_outT[(size_t)BB * TROUT];

// ---------------------------------------------------------------------------
// Kernel A: FIR pre-pass (unchanged from round 8)
// ---------------------------------------------------------------------------
__global__ void __launch_bounds__(128) fir_kernel(
    const float* __restrict__ cur,
    const float* __restrict__ a,
    const float* __restrict__ b_act,
    const float* __restrict__ max_cur,
    int T)
{
    __shared__ float sm[191][64];
    const int li = threadIdx.x & 63;
    const int th = threadIdx.x >> 6;
    const int i  = blockIdx.x * 64 + li;
    const int t0 = blockIdx.y * 128;

    float areg[64];
#pragma unroll
    for (int k = 0; k < 64; ++k) areg[k] = __ldg(&a[k]);
    const float bact   = __ldg(&b_act[0]);
    const float inv_mc = 1.0f / __ldg(&max_cur[0]);

#pragma unroll 4
    for (int rr = th; rr < 191; rr += 2) {
        int s = t0 - 63 + rr;
        sm[rr][li] = (s >= 0 && s < T) ? __ldg(&cur[(size_t)s * BB + i]) : 0.0f;
    }
    __syncthreads();

    float* myrow = g_qxT + (size_t)i * TR;
    const int tb = th * 64;

#pragma unroll 1
    for (int g = 0; g < 8; ++g) {
        const int tt = tb + g * 8;
        float acc[8];
#pragma unroll
        for (int o = 0; o < 8; ++o) acc[o] = 0.0f;
#pragma unroll
        for (int rr = 0; rr < 71; ++rr) {
            float v = sm[tt + rr][li];
#pragma unroll
            for (int o = 0; o < 8; ++o)
                if (rr >= o && rr <= o + 63)
                    acc[o] = fmaf(areg[rr - o], v, acc[o]);
        }
        const int t = t0 + tt;
        float r0 = (acc[0] - bact) * inv_mc, r1 = (acc[1] - bact) * inv_mc;
        float r2 = (acc[2] - bact) * inv_mc, r3 = (acc[3] - bact) * inv_mc;
        float r4 = (acc[4] - bact) * inv_mc, r5 = (acc[5] - bact) * inv_mc;
        float r6 = (acc[6] - bact) * inv_mc, r7 = (acc[7] - bact) * inv_mc;
        if (t + 7 < T) {
            *(float4*)(myrow + t)     = make_float4(r0, r1, r2, r3);
            *(float4*)(myrow + t + 4) = make_float4(r4, r5, r6, r7);
        } else {
            if (t + 0 < T) myrow[t + 0] = r0;
            if (t + 1 < T) myrow[t + 1] = r1;
            if (t + 2 < T) myrow[t + 2] = r2;
            if (t + 3 < T) myrow[t + 3] = r3;
            if (t + 4 < T) myrow[t + 4] = r4;
            if (t + 5 < T) myrow[t + 5] = r5;
            if (t + 6 < T) myrow[t + 6] = r6;
            if (t + 7 < T) myrow[t + 7] = r7;
        }
    }
}

// ---------------------------------------------------------------------------
// Kernel B: 16 lanes/element systolic ring (4 taps/lane), TWO elements per
// group software-interleaved (independent chains cover shfl/tanh latency).
// Lane r owns taps j=4r+d (d=1..4), ring R[4]:
//   d=1: patch-at-consume (lanes>0, prev broadcast) / W0z local fma (lane0)
//   d=2,3: scatter with broadcast thr
//   d=4: overwrite seed = hand-off from lane r+1 (4-step slack)
// Weights pre-multiplied by mfr so the chain ends at tanh -> scatter fma;
// relu hoisted before tanh (identical result, off-chain mul for output f).
// ---------------------------------------------------------------------------
#define STEP1(p, R, qv, fbv, thrPrev) { \
    float valF_ = fmaf(Wp, thrPrev, R[(p)&3]); \
    float hU_   = __shfl_down_sync(0xffffffffu, valF_, 1, 16); \
    float U_    = hU_ * u15; \
    float xx_   = valF_ + (qv); \
    float u_    = xx_ * xx_; \
    float s1_   = fmaf(c1, xx_, c0); \
    float s2_   = fmaf(c3, xx_, c2); \
    float pv_   = fmaf(u_, s2_, s1_); \
    float pr_   = fmaxf(pv_, 0.0f); \
    float th_;  asm("tanh.approx.f32 %0, %1;" : "=f"(th_) : "f"(pr_)); \
    R[((p)+1)&3] = fmaf(W0z, th_, R[((p)+1)&3]); \
    float tb_   = __shfl_sync(0xffffffffu, th_, 0, 16); \
    fbv[(p)&7]  = mfr * th_; \
    R[((p)+2)&3] = fmaf(W[1], tb_, R[((p)+2)&3]); \
    R[((p)+3)&3] = fmaf(W[2], tb_, R[((p)+3)&3]); \
    R[(p)&3]     = fmaf(W[3], tb_, U_); \
    thrPrev = tb_; \
}

#define STEP2(p, qvA, qvB) STEP1(p, RA, qvA, fbvA, thrPrevA) \
                           STEP1(p, RB, qvB, fbvB, thrPrevB)

#define S8X(aA, bA, aB, bB) \
    STEP2(0,(aA).x,(aB).x) STEP2(1,(aA).y,(aB).y) STEP2(2,(aA).z,(aB).z) STEP2(3,(aA).w,(aB).w) \
    STEP2(4,(bA).x,(bB).x) STEP2(5,(bA).y,(bB).y) STEP2(6,(bA).z,(bB).z) STEP2(7,(bA).w,(bB).w)

#define EMIT() if (r == 0) { \
        *(float4*)(optrA + 0) = make_float4(fbvA[0], fbvA[1], fbvA[2], fbvA[3]); \
        *(float4*)(optrA + 4) = make_float4(fbvA[4], fbvA[5], fbvA[6], fbvA[7]); \
        *(float4*)(optrB + 0) = make_float4(fbvB[0], fbvB[1], fbvB[2], fbvB[3]); \
        *(float4*)(optrB + 4) = make_float4(fbvB[4], fbvB[5], fbvB[6], fbvB[7]); \
    } \
    optrA += 8; optrB += 8;

__global__ void __launch_bounds__(128) rec_kernel(
    const float* __restrict__ b_lag,
    const float* __restrict__ poly_coeff,
    const float* __restrict__ max_cur,
    const float* __restrict__ max_fr,
    int T)
{
    const int tid = threadIdx.x;
    const int r   = tid & 15;                       // lane within 16-lane group
    const int g   = tid >> 4;                       // group 0..7
    const int eA  = blockIdx.x * 16 + g * 2;
    const int eB  = eA + 1;

    const float inv_mc = 1.0f / __ldg(&max_cur[0]);
    const float mfr    = __ldg(&max_fr[0]);
    float c0 = __ldg(&poly_coeff[0]); c0 *= c0;
    float c1 = __ldg(&poly_coeff[1]); c1 *= c1;
    float c2 = __ldg(&poly_coeff[2]); c2 *= c2;
    float c3 = __ldg(&poly_coeff[3]); c3 *= c3;
    const float cwm = 1000.0f * inv_mc * mfr;       // mfr folded into weights

    // lane r owns taps j = 4r+d (d=1..4); W[d-1] = mfr * cw * b_lag[64 - j]
    float W[4];
#pragma unroll
    for (int d = 1; d <= 4; ++d) W[d - 1] = cwm * __ldg(&b_lag[64 - 4 * r - d]);

    const float W0z = (r == 0)  ? W[0] : 0.0f;      // lane0: d=1 via local thr
    const float Wp  = (r == 0)  ? 0.0f : W[0];      // lanes>0: d=1 via consume patch
    const float u15 = (r == 15) ? 0.0f : 1.0f;      // hand-off mask

    float RA[4], RB[4];
#pragma unroll
    for (int k = 0; k < 4; ++k) { RA[k] = 0.0f; RB[k] = 0.0f; }
    float fbvA[8], fbvB[8];
    float thrPrevA = 0.0f, thrPrevB = 0.0f;

    const float4* qrowA = (const float4*)(g_qxT + (size_t)eA * TR);
    const float4* qrowB = (const float4*)(g_qxT + (size_t)eB * TR);
    float* optrA = g_outT + (size_t)eA * TROUT;
    float* optrB = g_outT + (size_t)eB * TROUT;

    float4 qaA = __ldg(qrowA + 0), qbA = __ldg(qrowA + 1);
    float4 qaB = __ldg(qrowB + 0), qbB = __ldg(qrowB + 1);

    const int nfull = T >> 3;
    const int npair = nfull >> 1;
    for (int m = 0; m < npair; ++m) {
        float4 naA = __ldg(qrowA + (size_t)(4 * m) + 2);
        float4 nbA = __ldg(qrowA + (size_t)(4 * m) + 3);
        float4 naB = __ldg(qrowB + (size_t)(4 * m) + 2);
        float4 nbB = __ldg(qrowB + (size_t)(4 * m) + 3);
        S8X(qaA, qbA, qaB, qbB)
        EMIT()
        qaA = __ldg(qrowA + (size_t)(4 * m) + 4);
        qbA = __ldg(qrowA + (size_t)(4 * m) + 5);
        qaB = __ldg(qrowB + (size_t)(4 * m) + 4);
        qbB = __ldg(qrowB + (size_t)(4 * m) + 5);
        S8X(naA, nbA, naB, nbB)
        EMIT()
    }
    if (nfull & 1) {
        S8X(qaA, qbA, qaB, qbB)
        EMIT()
    }

    // ---- generic tail (T mod 8 steps; empty for T=2000) ----
    const int t0tail = nfull * 8;
    const int tail   = T - t0tail;
    if (tail > 0) {
#pragma unroll 1
        for (int el = 0; el < 2; ++el) {
            const int e = (el == 0) ? eA : eB;
            float ringD[4];
#pragma unroll
            for (int k = 0; k < 4; ++k) ringD[k] = (el == 0) ? RA[k] : RB[k];
            float tp = (el == 0) ? thrPrevA : thrPrevB;
#pragma unroll 1
            for (int tt = 0; tt < tail; ++tt) {
                int t = t0tail + tt;
                int p = t & 3;
                float valF = fmaf(Wp, tp, ringD[p]);
                float hU   = __shfl_down_sync(0xffffffffu, valF, 1, 16);
                float U    = hU * u15;
                float xx   = valF + __ldg(g_qxT + (size_t)e * TR + t);
                float u_   = xx * xx;
                float s1_  = fmaf(c1, xx, c0);
                float s2_  = fmaf(c3, xx, c2);
                float pv   = fmaf(u_, s2_, s1_);
                float pr   = fmaxf(pv, 0.0f);
                float th; asm("tanh.approx.f32 %0, %1;" : "=f"(th) : "f"(pr));
                ringD[(p + 1) & 3] = fmaf(W0z, th, ringD[(p + 1) & 3]);
                float tb = __shfl_sync(0xffffffffu, th, 0, 16);
                if (r == 0) g_outT[(size_t)e * TROUT + t] = mfr * th;
                ringD[(p + 2) & 3] = fmaf(W[1], tb, ringD[(p + 2) & 3]);
                ringD[(p + 3) & 3] = fmaf(W[2], tb, ringD[(p + 3) & 3]);
                ringD[p] = fmaf(W[3], tb, U);
                tp = tb;
            }
        }
    }
}

// ---------------------------------------------------------------------------
// Kernel C: transpose g_outT[e][t] -> out[t][e]  (unchanged)
// ---------------------------------------------------------------------------
__global__ void __launch_bounds__(256) tr_kernel(float* __restrict__ out, int T)
{
    __shared__ float tile[32][33];
    const int tx = threadIdx.x, ty = threadIdx.y;
    const int e0 = blockIdx.x * 32;
    const int t0 = blockIdx.y * 32;

#pragma unroll
    for (int j = 0; j < 4; ++j) {
        int e = e0 + ty + 8 * j;
        int t = t0 + tx;
        tile[ty + 8 * j][tx] = (t < T) ? g_outT[(size_t)e * TROUT + t] : 0.0f;
    }
    __syncthreads();
#pragma unroll
    for (int j = 0; j < 4; ++j) {
        int t = t0 + ty + 8 * j;
        if (t < T) out[(size_t)t * BB + e0 + tx] = tile[tx][ty + 8 * j];
    }
}

// ---------------------------------------------------------------------------
extern "C" void kernel_launch(void* const* d_in, const int* in_sizes, int n_in,
                              void* d_out, int out_size)
{
    const float* currents = (const float*)d_in[0];
    const float* a        = (const float*)d_in[1];
    const float* b_lag    = (const float*)d_in[2];
    const float* poly     = (const float*)d_in[3];
    const float* b_act    = (const float*)d_in[4];
    const float* max_cur  = (const float*)d_in[5];
    const float* max_fr   = (const float*)d_in[6];
    float* out = (float*)d_out;

    const int T = in_sizes[0] / BB;   // 2000

    dim3 gA(BB / 64, (T + 127) / 128);
    fir_kernel<<<gA, 128>>>(currents, a, b_act, max_cur, T);

    // 16 lanes/element, 2 elements/group, 8 groups/block -> 128 blocks
    rec_kernel<<<BB / 16, 128>>>(b_lag, poly, max_cur, max_fr, T);

    dim3 gC(BB / 32, (T + 31) / 32);
    tr_kernel<<<gC, dim3(32, 8)>>>(out, T);
}

// round 10
// speedup vs baseline: 1.1026x; 1.1026x over previous
#include <cuda_runtime.h>

#define BB    2048
#define TR    2080   // row length of transposed qx (floats); rows zero-padded
#define TROUT 2048   // row length of transposed output

__device__ float g_qxT[(size_t)BB * TR];
__device__ float g_outT[(size_t)BB * TROUT];

// ---------------------------------------------------------------------------
// Kernel A: FIR pre-pass (unchanged from round 8)
// ---------------------------------------------------------------------------
__global__ void __launch_bounds__(128) fir_kernel(
    const float* __restrict__ cur,
    const float* __restrict__ a,
    const float* __restrict__ b_act,
    const float* __restrict__ max_cur,
    int T)
{
    __shared__ float sm[191][64];
    const int li = threadIdx.x & 63;
    const int th = threadIdx.x >> 6;
    const int i  = blockIdx.x * 64 + li;
    const int t0 = blockIdx.y * 128;

    float areg[64];
#pragma unroll
    for (int k = 0; k < 64; ++k) areg[k] = __ldg(&a[k]);
    const float bact   = __ldg(&b_act[0]);
    const float inv_mc = 1.0f / __ldg(&max_cur[0]);

#pragma unroll 4
    for (int rr = th; rr < 191; rr += 2) {
        int s = t0 - 63 + rr;
        sm[rr][li] = (s >= 0 && s < T) ? __ldg(&cur[(size_t)s * BB + i]) : 0.0f;
    }
    __syncthreads();

    float* myrow = g_qxT + (size_t)i * TR;
    const int tb = th * 64;

#pragma unroll 1
    for (int g = 0; g < 8; ++g) {
        const int tt = tb + g * 8;
        float acc[8];
#pragma unroll
        for (int o = 0; o < 8; ++o) acc[o] = 0.0f;
#pragma unroll
        for (int rr = 0; rr < 71; ++rr) {
            float v = sm[tt + rr][li];
#pragma unroll
            for (int o = 0; o < 8; ++o)
                if (rr >= o && rr <= o + 63)
                    acc[o] = fmaf(areg[rr - o], v, acc[o]);
        }
        const int t = t0 + tt;
        float r0 = (acc[0] - bact) * inv_mc, r1 = (acc[1] - bact) * inv_mc;
        float r2 = (acc[2] - bact) * inv_mc, r3 = (acc[3] - bact) * inv_mc;
        float r4 = (acc[4] - bact) * inv_mc, r5 = (acc[5] - bact) * inv_mc;
        float r6 = (acc[6] - bact) * inv_mc, r7 = (acc[7] - bact) * inv_mc;
        if (t + 7 < T) {
            *(float4*)(myrow + t)     = make_float4(r0, r1, r2, r3);
            *(float4*)(myrow + t + 4) = make_float4(r4, r5, r6, r7);
        } else {
            if (t + 0 < T) myrow[t + 0] = r0;
            if (t + 1 < T) myrow[t + 1] = r1;
            if (t + 2 < T) myrow[t + 2] = r2;
            if (t + 3 < T) myrow[t + 3] = r3;
            if (t + 4 < T) myrow[t + 4] = r4;
            if (t + 5 < T) myrow[t + 5] = r5;
            if (t + 6 < T) myrow[t + 6] = r6;
            if (t + 7 < T) myrow[t + 7] = r7;
        }
    }
}

// ---------------------------------------------------------------------------
// Kernel B: 8 lanes/element, ROTATED tap ownership -> shfl-free serial loop.
// Lane r owns taps j = 8r+3 .. 8r+10 (weights 0 for j>64), ring R[8].
// Slot for target tau lives on lane r for 8 steps, released at step tau-8r-2
// via shfl_down hand-off (8-step slack). All scatters use tbPrev = broadcast
// of th from one FULL step ago (>=1-step slack; k=0 writes the slot released
// this very step, before it is read -> ordering only, no latency).
// Lane0 adds taps 1,2 locally: y-pipeline of depth 2 carries the released
// slot (target s+2): +W2L*th(s) at step s, +W1L*th(s+1) at consume (s+2).
// Serial loop: th -> fma -> add q -> poly -> max -> tanh  (~36 cyc, no shfl).
// ---------------------------------------------------------------------------
#define STEP(p, qv) { \
    R[((p)+0)&7] = fmaf(W[0], tbPrev, R[((p)+0)&7]); \
    R[((p)+1)&7] = fmaf(W[1], tbPrev, R[((p)+1)&7]); \
    R[((p)+2)&7] = fmaf(W[2], tbPrev, R[((p)+2)&7]); \
    R[((p)+3)&7] = fmaf(W[3], tbPrev, R[((p)+3)&7]); \
    R[((p)+4)&7] = fmaf(W[4], tbPrev, R[((p)+4)&7]); \
    R[((p)+5)&7] = fmaf(W[5], tbPrev, R[((p)+5)&7]); \
    R[((p)+6)&7] = fmaf(W[6], tbPrev, R[((p)+6)&7]); \
    R[((p)+7)&7] = fmaf(W[7], tbPrev, R[((p)+7)&7]); \
    float valRel_ = R[(p)&7]; \
    float hU_ = __shfl_down_sync(0xffffffffu, valRel_, 1, 8); \
    float xx_ = fmaf(W1L, thPrev, y[(p)&1]) + (qv); \
    R[(p)&7] = hU_ * u7; \
    float u_  = xx_ * xx_; \
    float s1_ = fmaf(c1, xx_, c0); \
    float s2_ = fmaf(c3, xx_, c2); \
    float pv_ = fmaf(u_, s2_, s1_); \
    float pr_ = fmaxf(pv_, 0.0f); \
    float th_; asm("tanh.approx.f32 %0, %1;" : "=f"(th_) : "f"(pr_)); \
    fbv[(p)&7] = mfr * th_; \
    float tb_ = __shfl_sync(0xffffffffu, th_, 0, 8); \
    y[(p)&1] = fmaf(W2L, th_, valRel_); \
    thPrev = th_; \
    tbPrev = tb_; \
}

#define S8(qa, qb) STEP(0,(qa).x) STEP(1,(qa).y) STEP(2,(qa).z) STEP(3,(qa).w) \
                   STEP(4,(qb).x) STEP(5,(qb).y) STEP(6,(qb).z) STEP(7,(qb).w)

#define EMIT() if (r == 0) { \
        *(float4*)(optr + 0) = make_float4(fbv[0], fbv[1], fbv[2], fbv[3]); \
        *(float4*)(optr + 4) = make_float4(fbv[4], fbv[5], fbv[6], fbv[7]); \
    } \
    optr += 8;

__global__ void __launch_bounds__(128) rec_kernel(
    const float* __restrict__ b_lag,
    const float* __restrict__ poly_coeff,
    const float* __restrict__ max_cur,
    const float* __restrict__ max_fr,
    int T)
{
    const int tid = threadIdx.x;
    const int r   = tid & 7;                        // lane within 8-lane group
    const int e   = blockIdx.x * 16 + (tid >> 3);   // element index

    const float inv_mc = 1.0f / __ldg(&max_cur[0]);
    const float mfr    = __ldg(&max_fr[0]);
    float c0 = __ldg(&poly_coeff[0]); c0 *= c0;
    float c1 = __ldg(&poly_coeff[1]); c1 *= c1;
    float c2 = __ldg(&poly_coeff[2]); c2 *= c2;
    float c3 = __ldg(&poly_coeff[3]); c3 *= c3;
    const float cwm = 1000.0f * inv_mc * mfr;       // mfr folded into weights

    // lane r owns taps j = 8r+3+k (k=0..7); W[k] = cwm*b_lag[64-j], 0 if j>64
    float W[8];
#pragma unroll
    for (int k = 0; k < 8; ++k) {
        int j = 8 * r + 3 + k;
        W[k] = (j <= 64) ? cwm * __ldg(&b_lag[64 - j]) : 0.0f;
    }
    // lane0-only local taps 1, 2
    const float W1L = (r == 0) ? cwm * __ldg(&b_lag[63]) : 0.0f;
    const float W2L = (r == 0) ? cwm * __ldg(&b_lag[62]) : 0.0f;
    const float u7  = (r == 7) ? 0.0f : 1.0f;       // hand-off mask

    float R[8];
#pragma unroll
    for (int k = 0; k < 8; ++k) R[k] = 0.0f;
    float y[2] = {0.0f, 0.0f};
    float fbv[8];
    float thPrev = 0.0f, tbPrev = 0.0f;

    const float4* qrow = (const float4*)(g_qxT + (size_t)e * TR);
    float* optr = g_outT + (size_t)e * TROUT;

    float4 qa = __ldg(qrow + 0), qb = __ldg(qrow + 1);

    const int nfull = T >> 3;
    const int npair = nfull >> 1;
    for (int m = 0; m < npair; ++m) {
        float4 na = __ldg(qrow + (size_t)(4 * m) + 2);
        float4 nb = __ldg(qrow + (size_t)(4 * m) + 3);
        S8(qa, qb)
        EMIT()
        qa = __ldg(qrow + (size_t)(4 * m) + 4);
        qb = __ldg(qrow + (size_t)(4 * m) + 5);
        S8(na, nb)
        EMIT()
    }
    if (nfull & 1) {
        S8(qa, qb)
        EMIT()
    }

    // ---- generic tail (T mod 8 steps; empty for T=2000) ----
    const int t0tail = nfull * 8;
    const int tail   = T - t0tail;
    if (tail > 0) {
        float ringD[8];
#pragma unroll
        for (int k = 0; k < 8; ++k) ringD[k] = R[k];
#pragma unroll 1
        for (int tt = 0; tt < tail; ++tt) {
            int t = t0tail + tt;
            int p = t & 7;
#pragma unroll 1
            for (int k = 0; k < 8; ++k)
                ringD[(p + k) & 7] = fmaf(W[k], tbPrev, ringD[(p + k) & 7]);
            float valRel = ringD[p];
            float hU = __shfl_down_sync(0xffffffffu, valRel, 1, 8);
            float xx = fmaf(W1L, thPrev, y[p & 1]) + __ldg(g_qxT + (size_t)e * TR + t);
            ringD[p] = hU * u7;
            float u_  = xx * xx;
            float s1_ = fmaf(c1, xx, c0);
            float s2_ = fmaf(c3, xx, c2);
            float pv  = fmaf(u_, s2_, s1_);
            float pr  = fmaxf(pv, 0.0f);
            float th; asm("tanh.approx.f32 %0, %1;" : "=f"(th) : "f"(pr));
            if (r == 0) g_outT[(size_t)e * TROUT + t] = mfr * th;
            float tbn = __shfl_sync(0xffffffffu, th, 0, 8);
            y[p & 1] = fmaf(W2L, th, valRel);
            thPrev = th;
            tbPrev = tbn;
        }
    }
}

// ---------------------------------------------------------------------------
// Kernel C: transpose g_outT[e][t] -> out[t][e]  (unchanged)
// ---------------------------------------------------------------------------
__global__ void __launch_bounds__(256) tr_kernel(float* __restrict__ out, int T)
{
    __shared__ float tile[32][33];
    const int tx = threadIdx.x, ty = threadIdx.y;
    const int e0 = blockIdx.x * 32;
    const int t0 = blockIdx.y * 32;

#pragma unroll
    for (int j = 0; j < 4; ++j) {
        int e = e0 + ty + 8 * j;
        int t = t0 + tx;
        tile[ty + 8 * j][tx] = (t < T) ? g_outT[(size_t)e * TROUT + t] : 0.0f;
    }
    __syncthreads();
#pragma unroll
    for (int j = 0; j < 4; ++j) {
        int t = t0 + ty + 8 * j;
        if (t < T) out[(size_t)t * BB + e0 + tx] = tile[tx][ty + 8 * j];
    }
}

// ---------------------------------------------------------------------------
extern "C" void kernel_launch(void* const* d_in, const int* in_sizes, int n_in,
                              void* d_out, int out_size)
{
    const float* currents = (const float*)d_in[0];
    const float* a        = (const float*)d_in[1];
    const float* b_lag    = (const float*)d_in[2];
    const float* poly     = (const float*)d_in[3];
    const float* b_act    = (const float*)d_in[4];
    const float* max_cur  = (const float*)d_in[5];
    const float* max_fr   = (const float*)d_in[6];
    float* out = (float*)d_out;

    const int T = in_sizes[0] / BB;   // 2000

    dim3 gA(BB / 64, (T + 127) / 128);
    fir_kernel<<<gA, 128>>>(currents, a, b_act, max_cur, T);

    // 8 lanes/element, 16 elements per 128-thread block -> 128 blocks,
    // 512 warps -> exactly 1 warp per SMSP chip-wide.
    rec_kernel<<<BB / 16, 128>>>(b_lag, poly, max_cur, max_fr, T);

    dim3 gC(BB / 32, (T + 31) / 32);
    tr_kernel<<<gC, dim3(32, 8)>>>(out, T);
}

// round 11
// speedup vs baseline: 1.2872x; 1.1674x over previous
#include <cuda_runtime.h>

#define BB    2048
#define TR    2080   // row length of transposed qx (floats); rows zero-padded
#define TROUT 2048   // row length of transposed output

__device__ float g_qxT[(size_t)BB * TR];
__device__ float g_outT[(size_t)BB * TROUT];

// ---------------------------------------------------------------------------
// Kernel A: FIR pre-pass (unchanged from round 8)
// ---------------------------------------------------------------------------
__global__ void __launch_bounds__(128) fir_kernel(
    const float* __restrict__ cur,
    const float* __restrict__ a,
    const float* __restrict__ b_act,
    const float* __restrict__ max_cur,
    int T)
{
    __shared__ float sm[191][64];
    const int li = threadIdx.x & 63;
    const int th = threadIdx.x >> 6;
    const int i  = blockIdx.x * 64 + li;
    const int t0 = blockIdx.y * 128;

    float areg[64];
#pragma unroll
    for (int k = 0; k < 64; ++k) areg[k] = __ldg(&a[k]);
    const float bact   = __ldg(&b_act[0]);
    const float inv_mc = 1.0f / __ldg(&max_cur[0]);

#pragma unroll 4
    for (int rr = th; rr < 191; rr += 2) {
        int s = t0 - 63 + rr;
        sm[rr][li] = (s >= 0 && s < T) ? __ldg(&cur[(size_t)s * BB + i]) : 0.0f;
    }
    __syncthreads();

    float* myrow = g_qxT + (size_t)i * TR;
    const int tb = th * 64;

#pragma unroll 1
    for (int g = 0; g < 8; ++g) {
        const int tt = tb + g * 8;
        float acc[8];
#pragma unroll
        for (int o = 0; o < 8; ++o) acc[o] = 0.0f;
#pragma unroll
        for (int rr = 0; rr < 71; ++rr) {
            float v = sm[tt + rr][li];
#pragma unroll
            for (int o = 0; o < 8; ++o)
                if (rr >= o && rr <= o + 63)
                    acc[o] = fmaf(areg[rr - o], v, acc[o]);
        }
        const int t = t0 + tt;
        float r0 = (acc[0] - bact) * inv_mc, r1 = (acc[1] - bact) * inv_mc;
        float r2 = (acc[2] - bact) * inv_mc, r3 = (acc[3] - bact) * inv_mc;
        float r4 = (acc[4] - bact) * inv_mc, r5 = (acc[5] - bact) * inv_mc;
        float r6 = (acc[6] - bact) * inv_mc, r7 = (acc[7] - bact) * inv_mc;
        if (t + 7 < T) {
            *(float4*)(myrow + t)     = make_float4(r0, r1, r2, r3);
            *(float4*)(myrow + t + 4) = make_float4(r4, r5, r6, r7);
        } else {
            if (t + 0 < T) myrow[t + 0] = r0;
            if (t + 1 < T) myrow[t + 1] = r1;
            if (t + 2 < T) myrow[t + 2] = r2;
            if (t + 3 < T) myrow[t + 3] = r3;
            if (t + 4 < T) myrow[t + 4] = r4;
            if (t + 5 < T) myrow[t + 5] = r5;
            if (t + 6 < T) myrow[t + 6] = r6;
            if (t + 7 < T) myrow[t + 7] = r7;
        }
    }
}

// ---------------------------------------------------------------------------
// Kernel B: 8 lanes/element, rotated taps (j = 8r+3..8r+10), SOFTWARE-
// PIPELINED step: serial math first; all shfl consumers moved one full step
// after their producers (deferred seed via hUPrev, scatter via tbPrev).
// yq ring pre-adds the q value two steps early.
// Arithmetic identical to round 10.
// ---------------------------------------------------------------------------
#define STEP(p, qv2) { \
    /* 1. serial chain (only thPrev + yq inputs) */ \
    float xx_ = fmaf(W1L, thPrev, yq[(p)&1]); \
    float u_  = xx_ * xx_; \
    float s1_ = fmaf(c1, xx_, c0); \
    float s2_ = fmaf(c3, xx_, c2); \
    float pv_ = fmaf(u_, s2_, s1_); \
    float pr_ = fmaxf(pv_, 0.0f); \
    float th_; asm("tanh.approx.f32 %0, %1;" : "=f"(th_) : "f"(pr_)); \
    fbv[(p)&7] = mfr * th_; \
    float tb_ = __shfl_sync(0xffffffffu, th_, 0, 8); \
    /* 2. deferred seed for slot released LAST step (shfl_down ~1 step old) */ \
    R[((p)+7)&7] = hUPrev * u7; \
    /* 3. scatter with tbPrev (shfl issued after last step's tanh) */ \
    R[((p)+0)&7] = fmaf(W[0], tbPrev, R[((p)+0)&7]); \
    R[((p)+1)&7] = fmaf(W[1], tbPrev, R[((p)+1)&7]); \
    R[((p)+2)&7] = fmaf(W[2], tbPrev, R[((p)+2)&7]); \
    R[((p)+3)&7] = fmaf(W[3], tbPrev, R[((p)+3)&7]); \
    R[((p)+4)&7] = fmaf(W[4], tbPrev, R[((p)+4)&7]); \
    R[((p)+5)&7] = fmaf(W[5], tbPrev, R[((p)+5)&7]); \
    R[((p)+6)&7] = fmaf(W[6], tbPrev, R[((p)+6)&7]); \
    R[((p)+7)&7] = fmaf(W[7], tbPrev, R[((p)+7)&7]); \
    /* 4. release + next hand-off + y/yq update */ \
    float valRel_ = R[(p)&7]; \
    float hU_ = __shfl_down_sync(0xffffffffu, valRel_, 1, 8); \
    float y_  = fmaf(W2L, th_, valRel_); \
    yq[(p)&1] = y_ + (qv2); \
    thPrev = th_; \
    tbPrev = tb_; \
    hUPrev = hU_; \
}

#define S8(qa, qb, nx) \
    STEP(0,(qa).z) STEP(1,(qa).w) STEP(2,(qb).x) STEP(3,(qb).y) \
    STEP(4,(qb).z) STEP(5,(qb).w) STEP(6,(nx).x) STEP(7,(nx).y)

#define EMIT() if (r == 0) { \
        *(float4*)(optr + 0) = make_float4(fbv[0], fbv[1], fbv[2], fbv[3]); \
        *(float4*)(optr + 4) = make_float4(fbv[4], fbv[5], fbv[6], fbv[7]); \
    } \
    optr += 8;

__global__ void __launch_bounds__(128) rec_kernel(
    const float* __restrict__ b_lag,
    const float* __restrict__ poly_coeff,
    const float* __restrict__ max_cur,
    const float* __restrict__ max_fr,
    int T)
{
    const int tid = threadIdx.x;
    const int r   = tid & 7;
    const int e   = blockIdx.x * 16 + (tid >> 3);

    const float inv_mc = 1.0f / __ldg(&max_cur[0]);
    const float mfr    = __ldg(&max_fr[0]);
    float c0 = __ldg(&poly_coeff[0]); c0 *= c0;
    float c1 = __ldg(&poly_coeff[1]); c1 *= c1;
    float c2 = __ldg(&poly_coeff[2]); c2 *= c2;
    float c3 = __ldg(&poly_coeff[3]); c3 *= c3;
    const float cwm = 1000.0f * inv_mc * mfr;

    // lane r owns taps j = 8r+3+k (k=0..7); W[k] = cwm*b_lag[64-j], 0 if j>64
    float W[8];
#pragma unroll
    for (int k = 0; k < 8; ++k) {
        int j = 8 * r + 3 + k;
        W[k] = (j <= 64) ? cwm * __ldg(&b_lag[64 - j]) : 0.0f;
    }
    const float W1L = (r == 0) ? cwm * __ldg(&b_lag[63]) : 0.0f;
    const float W2L = (r == 0) ? cwm * __ldg(&b_lag[62]) : 0.0f;
    const float u7  = (r == 7) ? 0.0f : 1.0f;

    float R[8];
#pragma unroll
    for (int k = 0; k < 8; ++k) R[k] = 0.0f;
    float fbv[8];
    float thPrev = 0.0f, tbPrev = 0.0f, hUPrev = 0.0f;

    const float4* qrow = (const float4*)(g_qxT + (size_t)e * TR);
    float* optr = g_outT + (size_t)e * TROUT;

    float4 qa = __ldg(qrow + 0), qb = __ldg(qrow + 1);

    // yq[i] = y + q(t) pre-added; initially y=0
    float yq[2] = { qa.x, qa.y };

    const int nfull = T >> 3;
    const int npair = nfull >> 1;
    for (int m = 0; m < npair; ++m) {
        float4 na = __ldg(qrow + (size_t)(4 * m) + 2);
        float4 nb = __ldg(qrow + (size_t)(4 * m) + 3);
        S8(qa, qb, na)          // block 2m (steps 6,7 pre-add next block's q)
        EMIT()
        qa = __ldg(qrow + (size_t)(4 * m) + 4);
        qb = __ldg(qrow + (size_t)(4 * m) + 5);
        S8(na, nb, qa)          // block 2m+1
        EMIT()
    }
    if (nfull & 1) {
        float4 nq = __ldg(qrow + (size_t)(2 * nfull));   // zero-padded, safe
        S8(qa, qb, nq)
        EMIT()
    }

    // ---- generic tail (T mod 8 steps; empty for T=2000) ----
    const int t0tail = nfull * 8;
    const int tail   = T - t0tail;
    if (tail > 0) {
#pragma unroll 1
        for (int tt = 0; tt < tail; ++tt) {
            int t = t0tail + tt;
            int p = t & 7;
            float xx = fmaf(W1L, thPrev, yq[p & 1]);
            float u_  = xx * xx;
            float s1_ = fmaf(c1, xx, c0);
            float s2_ = fmaf(c3, xx, c2);
            float pv  = fmaf(u_, s2_, s1_);
            float pr  = fmaxf(pv, 0.0f);
            float th; asm("tanh.approx.f32 %0, %1;" : "=f"(th) : "f"(pr));
            if (r == 0) g_outT[(size_t)e * TROUT + t] = mfr * th;
            float tbn = __shfl_sync(0xffffffffu, th, 0, 8);
            R[(p + 7) & 7] = hUPrev * u7;          // deferred seed
#pragma unroll 1
            for (int k = 0; k < 8; ++k)
                R[(p + k) & 7] = fmaf(W[k], tbPrev, R[(p + k) & 7]);
            float valRel = R[p];
            float hU = __shfl_down_sync(0xffffffffu, valRel, 1, 8);
            float y_ = fmaf(W2L, th, valRel);
            yq[p & 1] = y_ + __ldg(g_qxT + (size_t)e * TR + (t + 2)); // padded
            thPrev = th; tbPrev = tbn; hUPrev = hU;
        }
    }
}

// ---------------------------------------------------------------------------
// Kernel C: transpose g_outT[e][t] -> out[t][e]  (unchanged)
// ---------------------------------------------------------------------------
__global__ void __launch_bounds__(256) tr_kernel(float* __restrict__ out, int T)
{
    __shared__ float tile[32][33];
    const int tx = threadIdx.x, ty = threadIdx.y;
    const int e0 = blockIdx.x * 32;
    const int t0 = blockIdx.y * 32;

#pragma unroll
    for (int j = 0; j < 4; ++j) {
        int e = e0 + ty + 8 * j;
        int t = t0 + tx;
        tile[ty + 8 * j][tx] = (t < T) ? g_outT[(size_t)e * TROUT + t] : 0.0f;
    }
    __syncthreads();
#pragma unroll
    for (int j = 0; j < 4; ++j) {
        int t = t0 + ty + 8 * j;
        if (t < T) out[(size_t)t * BB + e0 + tx] = tile[tx][ty + 8 * j];
    }
}

// ---------------------------------------------------------------------------
extern "C" void kernel_launch(void* const* d_in, const int* in_sizes, int n_in,
                              void* d_out, int out_size)
{
    const float* currents = (const float*)d_in[0];
    const float* a        = (const float*)d_in[1];
    const float* b_lag    = (const float*)d_in[2];
    const float* poly     = (const float*)d_in[3];
    const float* b_act    = (const float*)d_in[4];
    const float* max_cur  = (const float*)d_in[5];
    const float* max_fr   = (const float*)d_in[6];
    float* out = (float*)d_out;

    const int T = in_sizes[0] / BB;   // 2000

    dim3 gA(BB / 64, (T + 127) / 128);
    fir_kernel<<<gA, 128>>>(currents, a, b_act, max_cur, T);

    // 8 lanes/element, 16 elements/block -> 128 blocks, 1 warp per SMSP
    rec_kernel<<<BB / 16, 128>>>(b_lag, poly, max_cur, max_fr, T);

    dim3 gC(BB / 32, (T + 31) / 32);
    tr_kernel<<<gC, dim3(32, 8)>>>(out, T);
}